// round 14
// baseline (speedup 1.0000x reference)
#include <cuda_runtime.h>
#include <cuda_fp16.h>
#include <math.h>
#include <float.h>
#include <limits.h>
#include <stdint.h>

// Problem constants
#define B_     2048
#define N_     65536
#define F_     128
#define KSTEPS (F_ / 16)       // 8 (fp16 mma k16)
#define NSPLIT 37              // 16 x 37 = 592 CTAs = exactly 2 waves at occ 2
#define BN     64
#define NLBL   10
#define MARGIN2 0.5f           // phase-2 margin (>=5x fp16 vhat error bound)
#define PTOP   4               // tensor per-thread top depth
#define TPC    8               // keys kept per (row, split)
#define NPART  (NSPLIT * TPC)  // 296

// Work split: 1024 column-tiles per m-block.
// 19 tensor CTAs cover tiles [0, 812); 18 SIMT CTAs cover [812, 1024).
#define TEN_TILES 812
#define SIM_TILES 212

// Tensor-role smem layout
#define KPH    136             // padded row stride in halfs (272B)
#define KPB    (KPH * 2)
#define AS_BYTES (128 * KPB)   // 34816
#define BS_BYTES (64 * KPB)    // 17408
// SIMT-role smem layout: As fp32 k-major 64KB @0, Bs fp32 [64][132] @65536
#define SIM_BS_OFF 65536
#define SMEM_TOTAL 99328       // max(tensor 69632, simt 99328)

// ---------------------------------------------------------------------------
// Static device scratch
// ---------------------------------------------------------------------------
__device__ __align__(16) __half g_xe[(size_t)B_ * F_];   // fp16(x*feat)
__device__ __align__(16) __half g_te[(size_t)N_ * F_];   // fp16(tr*feat)
__device__ __align__(16) float  g_xf[(size_t)B_ * F_];   // fp32(x*feat)
__device__ float g_left[B_];
__device__ float g_right[N_];
__device__ unsigned long long g_part[(size_t)B_ * NPART]; // sortable keys

// ---------------------------------------------------------------------------
// Helpers
// ---------------------------------------------------------------------------
__device__ __forceinline__ uint32_t smem_u32(const void* p) {
    uint32_t a;
    asm("{ .reg .u64 t; cvta.to.shared.u64 t, %1; cvt.u32.u64 %0, t; }" : "=r"(a) : "l"(p));
    return a;
}
#define CP16(dst, src) \
    asm volatile("cp.async.cg.shared.global [%0], [%1], 16;" :: "r"(dst), "l"(src))
#define CPCOMMIT() asm volatile("cp.async.commit_group;" ::: "memory")
#define CPWAIT(n)  asm volatile("cp.async.wait_group %0;" :: "n"(n) : "memory")

#define LDSM4(r0, r1, r2, r3, addr) \
    asm volatile("ldmatrix.sync.aligned.m8n8.x4.shared.b16 {%0,%1,%2,%3}, [%4];" \
                 : "=r"(r0), "=r"(r1), "=r"(r2), "=r"(r3) : "r"(addr))

#define MMA16816(c, a, b0, b1) \
    asm volatile("mma.sync.aligned.m16n8k16.row.col.f32.f16.f16.f32 " \
                 "{%0,%1,%2,%3},{%4,%5,%6,%7},{%8,%9},{%0,%1,%2,%3};" \
                 : "+f"((c)[0]), "+f"((c)[1]), "+f"((c)[2]), "+f"((c)[3]) \
                 : "r"((a)[0]), "r"((a)[1]), "r"((a)[2]), "r"((a)[3]), \
                   "r"(b0), "r"(b1))

// Order-preserving float<->uint maps (exact bit round-trip)
__device__ __forceinline__ unsigned ordf(float v) {
    unsigned u = __float_as_uint(v);
    return (u & 0x80000000u) ? ~u : (u | 0x80000000u);
}
__device__ __forceinline__ float unordf(unsigned u) {
    return __uint_as_float((u & 0x80000000u) ? (u ^ 0x80000000u) : ~u);
}
// key order == jax top_k order: higher v wins; ties -> lower idx wins
__device__ __forceinline__ unsigned long long mkkey(float v, int i) {
    return ((unsigned long long)ordf(v) << 32) | (unsigned)(~i);
}
__device__ __forceinline__ bool better(float v, int i, float bv, int bi) {
    return (v > bv) || (v == bv && i < bi);
}
__device__ __forceinline__ void ins3(unsigned long long* s, unsigned long long k) {
    if (k > s[2]) {
        s[2] = k;
        if (s[2] > s[1]) { unsigned long long t = s[1]; s[1] = s[2]; s[2] = t; }
        if (s[1] > s[0]) { unsigned long long t = s[0]; s[0] = s[1]; s[1] = t; }
    }
}
// Block-wide top-3 key reduction (256 threads). tid 0 ends with global top-3.
__device__ __forceinline__ void top3_reduce(unsigned long long* s,
                                            unsigned long long* wbuf, int tid) {
    #pragma unroll
    for (int off = 16; off; off >>= 1) {
        unsigned long long r0 = __shfl_xor_sync(0xffffffffu, s[0], off);
        unsigned long long r1 = __shfl_xor_sync(0xffffffffu, s[1], off);
        unsigned long long r2 = __shfl_xor_sync(0xffffffffu, s[2], off);
        ins3(s, r0); ins3(s, r1); ins3(s, r2);
    }
    int w = tid >> 5, lane = tid & 31;
    if (lane == 0) { wbuf[w * 3] = s[0]; wbuf[w * 3 + 1] = s[1]; wbuf[w * 3 + 2] = s[2]; }
    __syncthreads();
    if (tid == 0)
        for (int i = 3; i < 24; i++) ins3(s, wbuf[i]);
}

// ---------------------------------------------------------------------------
// Prep: fp16 + fp32 of x*feat, fp16 of tr*feat, fp32 norms. One warp per row.
// ---------------------------------------------------------------------------
__global__ void prep_kernel(const float* __restrict__ x,
                            const float* __restrict__ tr,
                            const float* __restrict__ feat) {
    int g    = blockIdx.x * blockDim.x + threadIdx.x;
    int w    = g >> 5;
    int lane = threadIdx.x & 31;
    float4 f = ((const float4*)feat)[lane];

    float wv[4];
    bool isx = (w < B_);
    int row;
    if (isx) {
        row = w;
        float4 v = ((const float4*)x)[row * 32 + lane];
        wv[0] = v.x * f.x; wv[1] = v.y * f.y; wv[2] = v.z * f.z; wv[3] = v.w * f.w;
        float s = v.x * v.x + v.y * v.y + v.z * v.z + v.w * v.w;  // raw x^2
        #pragma unroll
        for (int o = 16; o; o >>= 1) s += __shfl_xor_sync(0xffffffffu, s, o);
        if (lane == 0) g_left[row] = s;
        ((float4*)g_xf)[row * 32 + lane] = make_float4(wv[0], wv[1], wv[2], wv[3]);
    } else if (w < B_ + N_) {
        row = w - B_;
        float4 v = ((const float4*)tr)[(size_t)row * 32 + lane];
        wv[0] = v.x * f.x; wv[1] = v.y * f.y; wv[2] = v.z * f.z; wv[3] = v.w * f.w;
        float s = wv[0]*wv[0] + wv[1]*wv[1] + wv[2]*wv[2] + wv[3]*wv[3];
        #pragma unroll
        for (int o = 16; o; o >>= 1) s += __shfl_xor_sync(0xffffffffu, s, o);
        if (lane == 0) g_right[row] = s;
    } else {
        return;
    }

    ushort4 th_;
    unsigned short* ph = &th_.x;
    #pragma unroll
    for (int j = 0; j < 4; j++) ph[j] = __half_as_ushort(__float2half_rn(wv[j]));
    size_t base = (size_t)row * F_ + lane * 4;
    if (isx) *(ushort4*)&g_xe[base] = th_;
    else     *(ushort4*)&g_te[base] = th_;
}

// ---------------------------------------------------------------------------
// Hybrid phase 1: even blockIdx.y -> fp16 HMMA GEMM (tensor pipe);
// odd blockIdx.y -> fp32 SIMT GEMM (fma pipe). Both produce top-TPC keys
// per (row, split). Grid (16, 37), 256 threads, occ 2 => 2 exact waves with
// role-alternating co-residency per SM.
// ---------------------------------------------------------------------------
__global__ __launch_bounds__(256, 2) void knn_hybrid(const float* __restrict__ tr) {
    extern __shared__ char smem[];
    const int tid  = threadIdx.x;
    const int mblk = blockIdx.x;
    const int y    = blockIdx.y;

    if ((y & 1) == 0) {
        // ================= TENSOR ROLE (fp16 mma.sync) =====================
        const uint32_t asB  = smem_u32(smem);
        const uint32_t bsB0 = asB + AS_BYTES;
        const int lane = tid & 31;
        const int wid  = tid >> 5;
        const int wm   = wid & 3;
        const int wn   = wid >> 2;
        const int ti   = y >> 1;                       // 0..18
        const int tstart = ti * 42 + min(ti, 14);      // 812 tiles over 19 CTAs
        const int tcount = 42 + (ti < 14 ? 1 : 0);

        // cp.async A block (128 x 128 halfs)
        {
            const __half* src = g_xe + (size_t)mblk * 128 * F_;
            #pragma unroll
            for (int j = 0; j < 8; j++) {
                int i = tid + j * 256;
                int row = i >> 4, kc = i & 15;
                CP16(asB + row * KPB + kc * 16, src + (size_t)row * F_ + kc * 8);
            }
        }
        // B tile 0
        {
            int nb0 = tstart * BN;
            #pragma unroll
            for (int j = 0; j < 4; j++) {
                int i = tid + j * 256;
                int row = i >> 4, kc = i & 15;
                CP16(bsB0 + row * KPB + kc * 16,
                     g_te + (size_t)(nb0 + row) * F_ + kc * 8);
            }
        }
        CPCOMMIT();

        float lft[4];
        float bv[4][PTOP];
        int   bi[4][PTOP];
        #pragma unroll
        for (int r = 0; r < 4; r++) {
            int mt = r >> 1, cp = r & 1;
            lft[r] = g_left[mblk * 128 + wm * 32 + mt * 16 + cp * 8 + (lane >> 2)];
            #pragma unroll
            for (int s = 0; s < PTOP; s++) { bv[r][s] = -FLT_MAX; bi[r][s] = INT_MAX; }
        }

        const uint32_t laneA = (uint32_t)((((lane >> 3) & 1) * 8 + (lane & 7)) * KPB
                                          + (lane >> 4) * 16);
        const uint32_t laneB = (uint32_t)((((lane >> 4) << 3) + (lane & 7)) * KPB
                                          + ((lane >> 3) & 1) * 16);
        const uint32_t aAddr0 = asB + (wm * 32) * KPB + laneA;
        const uint32_t aAddr1 = asB + (wm * 32 + 16) * KPB + laneA;

        for (int t = 0; t < tcount; t++) {
            if (t + 1 < tcount) {
                uint32_t bsN = bsB0 + ((t + 1) & 1) * BS_BYTES;
                int nb = (tstart + t + 1) * BN;
                #pragma unroll
                for (int j = 0; j < 4; j++) {
                    int i = tid + j * 256;
                    int row = i >> 4, kc = i & 15;
                    CP16(bsN + row * KPB + kc * 16,
                         g_te + (size_t)(nb + row) * F_ + kc * 8);
                }
                CPCOMMIT();
                CPWAIT(1);
            } else {
                CPWAIT(0);
            }
            __syncthreads();

            const uint32_t bsS = bsB0 + (t & 1) * BS_BYTES;
            const uint32_t bAddr0 = bsS + (wn * 32) * KPB + laneB;
            const uint32_t bAddr1 = bsS + (wn * 32 + 16) * KPB + laneB;

            float acc[2][4][4];
            #pragma unroll
            for (int mt = 0; mt < 2; mt++)
                #pragma unroll
                for (int nt = 0; nt < 4; nt++)
                    #pragma unroll
                    for (int c = 0; c < 4; c++) acc[mt][nt][c] = 0.0f;

            #pragma unroll
            for (int ks = 0; ks < KSTEPS; ks++) {
                const uint32_t ko = ks * 32;
                uint32_t a0[4], a1[4], b01[4], b23[4];
                LDSM4(a0[0], a0[1], a0[2], a0[3], aAddr0 + ko);
                LDSM4(a1[0], a1[1], a1[2], a1[3], aAddr1 + ko);
                LDSM4(b01[0], b01[1], b01[2], b01[3], bAddr0 + ko);
                LDSM4(b23[0], b23[1], b23[2], b23[3], bAddr1 + ko);
                MMA16816(acc[0][0], a0, b01[0], b01[1]);
                MMA16816(acc[0][1], a0, b01[2], b01[3]);
                MMA16816(acc[0][2], a0, b23[0], b23[1]);
                MMA16816(acc[0][3], a0, b23[2], b23[3]);
                MMA16816(acc[1][0], a1, b01[0], b01[1]);
                MMA16816(acc[1][1], a1, b01[2], b01[3]);
                MMA16816(acc[1][2], a1, b23[0], b23[1]);
                MMA16816(acc[1][3], a1, b23[2], b23[3]);
            }

            const int cbase = (tstart + t) * BN + wn * 32;
            float2 rt2[4];
            const float2* rp = (const float2*)(g_right + cbase + 2 * (lane & 3));
            #pragma unroll
            for (int nt = 0; nt < 4; nt++) rt2[nt] = __ldg(rp + nt * 4);

            float rm = fminf(fminf(fminf(rt2[0].x, rt2[0].y), fminf(rt2[1].x, rt2[1].y)),
                             fminf(fminf(rt2[2].x, rt2[2].y), fminf(rt2[3].x, rt2[3].y)));
            #pragma unroll
            for (int o = 16; o; o >>= 1)
                rm = fminf(rm, __shfl_xor_sync(0xffffffffu, rm, o));

            float subnd[4];
            #pragma unroll
            for (int r = 0; r < 4; r++) subnd[r] = sqrtf(lft[r] + rm);

            #pragma unroll
            for (int mt = 0; mt < 2; mt++) {
                #pragma unroll
                for (int nt = 0; nt < 4; nt++) {
                    const int colb = cbase + nt * 8 + 2 * (lane & 3);
                    #pragma unroll
                    for (int e = 0; e < 4; e++) {
                        const int r   = mt * 2 + (e >> 1);
                        const int idx = colb + (e & 1);
                        const float rt = (e & 1) ? rt2[nt].y : rt2[nt].x;
                        float a  = acc[mt][nt][(e >> 1) * 2 + (e & 1)];
                        float ub = fmaf(2.0f, a, -subnd[r]);
                        if (ub > bv[r][PTOP - 1]) {
                            float v = fmaf(2.0f, a, -sqrtf(lft[r] + rt));
                            if (v > bv[r][PTOP - 1]) {
                                bv[r][PTOP - 1] = v; bi[r][PTOP - 1] = idx;
                                #pragma unroll
                                for (int p = PTOP - 1; p > 0; p--) {
                                    if (bv[r][p] > bv[r][p - 1]) {
                                        float tv = bv[r][p - 1]; int tix = bi[r][p - 1];
                                        bv[r][p - 1] = bv[r][p]; bi[r][p - 1] = bi[r][p];
                                        bv[r][p] = tv;           bi[r][p] = tix;
                                    }
                                }
                            }
                        }
                    }
                }
            }
            __syncthreads();
        }

        // CTA merge: 8 threads x 4 entries -> top-8 keys per row
        unsigned long long* mrg = (unsigned long long*)smem;  // [128][32]
        const int slotb = (wn * 4 + (lane & 3)) * PTOP;
        #pragma unroll
        for (int r = 0; r < 4; r++) {
            int mt = r >> 1, cp = r & 1;
            int row = wm * 32 + mt * 16 + cp * 8 + (lane >> 2);
            #pragma unroll
            for (int s = 0; s < PTOP; s++)
                mrg[row * 32 + slotb + s] = mkkey(bv[r][s], bi[r][s]);
        }
        __syncthreads();

        if (tid < 128) {
            unsigned long long tv[TPC];
            #pragma unroll
            for (int s = 0; s < TPC; s++) tv[s] = 0ull;
            #pragma unroll 4
            for (int c = 0; c < 32; c++) {
                unsigned long long k = mrg[tid * 32 + c];
                if (k > tv[TPC - 1]) {
                    tv[TPC - 1] = k;
                    #pragma unroll
                    for (int p = TPC - 1; p > 0; p--) {
                        if (tv[p] > tv[p - 1]) {
                            unsigned long long t2 = tv[p - 1];
                            tv[p - 1] = tv[p]; tv[p] = t2;
                        }
                    }
                }
            }
            size_t gb = ((size_t)(mblk * 128 + tid) * NSPLIT + y) * TPC;
            #pragma unroll
            for (int s = 0; s < TPC; s++) g_part[gb + s] = tv[s];
        }
    } else {
        // ================= SIMT ROLE (fp32 FFMA) ===========================
        float* As = (float*)smem;                     // [k*128 + row]
        float* Bs = (float*)(smem + SIM_BS_OFF);      // [col*132 + k]
        const int tx = tid & 15;
        const int ty = tid >> 4;
        const int si = y >> 1;                         // 0..17
        const int sstart = TEN_TILES + si * 11 + min(si, 14);  // 212 tiles / 18 CTAs
        const int scount = 11 + (si < 14 ? 1 : 0);

        // Load A block (128 x 128 fp32) transposed into k-major smem
        for (int i = tid; i < 128 * 32; i += 256) {
            int row = i & 127, k4 = i >> 7;
            float4 v = ((const float4*)g_xf)[(mblk * 128 + row) * 32 + k4];
            As[(k4 * 4 + 0) * 128 + row] = v.x;
            As[(k4 * 4 + 1) * 128 + row] = v.y;
            As[(k4 * 4 + 2) * 128 + row] = v.z;
            As[(k4 * 4 + 3) * 128 + row] = v.w;
        }

        float lft[8];
        float bv[8][3];
        int   bi[8][3];
        #pragma unroll
        for (int j = 0; j < 8; j++) {
            int row = (j < 4) ? (tx * 4 + j) : (64 + tx * 4 + (j - 4));
            lft[j] = g_left[mblk * 128 + row];
            #pragma unroll
            for (int s = 0; s < 3; s++) { bv[j][s] = -FLT_MAX; bi[j][s] = INT_MAX; }
        }

        for (int t = 0; t < scount; t++) {
            const int nbase = (sstart + t) * BN;
            __syncthreads();
            for (int i = tid; i < 64 * 32; i += 256) {
                int col = i >> 5, k4 = i & 31;
                float4 v = ((const float4*)tr)[(size_t)(nbase + col) * 32 + k4];
                *(float4*)&Bs[col * 132 + k4 * 4] = v;
            }
            __syncthreads();

            float acc[8][4];
            #pragma unroll
            for (int j = 0; j < 8; j++)
                #pragma unroll
                for (int c = 0; c < 4; c++) acc[j][c] = 0.0f;

            #pragma unroll 8
            for (int k = 0; k < 128; k++) {
                float4 a0 = *(const float4*)&As[k * 128 + tx * 4];
                float4 a1 = *(const float4*)&As[k * 128 + 64 + tx * 4];
                float b0 = Bs[(ty * 4 + 0) * 132 + k];
                float b1 = Bs[(ty * 4 + 1) * 132 + k];
                float b2 = Bs[(ty * 4 + 2) * 132 + k];
                float b3 = Bs[(ty * 4 + 3) * 132 + k];
                acc[0][0] += a0.x * b0; acc[0][1] += a0.x * b1; acc[0][2] += a0.x * b2; acc[0][3] += a0.x * b3;
                acc[1][0] += a0.y * b0; acc[1][1] += a0.y * b1; acc[1][2] += a0.y * b2; acc[1][3] += a0.y * b3;
                acc[2][0] += a0.z * b0; acc[2][1] += a0.z * b1; acc[2][2] += a0.z * b2; acc[2][3] += a0.z * b3;
                acc[3][0] += a0.w * b0; acc[3][1] += a0.w * b1; acc[3][2] += a0.w * b2; acc[3][3] += a0.w * b3;
                acc[4][0] += a1.x * b0; acc[4][1] += a1.x * b1; acc[4][2] += a1.x * b2; acc[4][3] += a1.x * b3;
                acc[5][0] += a1.y * b0; acc[5][1] += a1.y * b1; acc[5][2] += a1.y * b2; acc[5][3] += a1.y * b3;
                acc[6][0] += a1.z * b0; acc[6][1] += a1.z * b1; acc[6][2] += a1.z * b2; acc[6][3] += a1.z * b3;
                acc[7][0] += a1.w * b0; acc[7][1] += a1.w * b1; acc[7][2] += a1.w * b2; acc[7][3] += a1.w * b3;
            }

            // Epilogue: v (exact fp32 assoc.) -> per-row top-3 with tie rules
            #pragma unroll
            for (int c = 0; c < 4; c++) {
                int idx  = nbase + ty * 4 + c;
                float rt = g_right[idx];
                #pragma unroll
                for (int j = 0; j < 8; j++) {
                    float v = fmaf(2.0f, acc[j][c], -sqrtf(lft[j] + rt));
                    if (better(v, idx, bv[j][2], bi[j][2])) {
                        bv[j][2] = v; bi[j][2] = idx;
                        if (better(bv[j][2], bi[j][2], bv[j][1], bi[j][1])) {
                            float tv = bv[j][1]; int tix = bi[j][1];
                            bv[j][1] = bv[j][2]; bi[j][1] = bi[j][2];
                            bv[j][2] = tv;       bi[j][2] = tix;
                            if (better(bv[j][1], bi[j][1], bv[j][0], bi[j][0])) {
                                tv = bv[j][0]; tix = bi[j][0];
                                bv[j][0] = bv[j][1]; bi[j][0] = bi[j][1];
                                bv[j][1] = tv;       bi[j][1] = tix;
                            }
                        }
                    }
                }
            }
        }

        // CTA merge: 16 ty-threads x 3 entries -> top-8 keys per row
        __syncthreads();
        unsigned long long* mrg = (unsigned long long*)smem;  // [128][48] = 49KB
        #pragma unroll
        for (int j = 0; j < 8; j++) {
            int row = (j < 4) ? (tx * 4 + j) : (64 + tx * 4 + (j - 4));
            #pragma unroll
            for (int s = 0; s < 3; s++)
                mrg[row * 48 + ty * 3 + s] = mkkey(bv[j][s], bi[j][s]);
        }
        __syncthreads();

        if (tid < 128) {
            unsigned long long tv[TPC];
            #pragma unroll
            for (int s = 0; s < TPC; s++) tv[s] = 0ull;
            #pragma unroll 4
            for (int c = 0; c < 48; c++) {
                unsigned long long k = mrg[tid * 48 + c];
                if (k > tv[TPC - 1]) {
                    tv[TPC - 1] = k;
                    #pragma unroll
                    for (int p = TPC - 1; p > 0; p--) {
                        if (tv[p] > tv[p - 1]) {
                            unsigned long long t2 = tv[p - 1];
                            tv[p - 1] = tv[p]; tv[p] = t2;
                        }
                    }
                }
            }
            size_t gb = ((size_t)(mblk * 128 + tid) * NSPLIT + y) * TPC;
            #pragma unroll
            for (int s = 0; s < TPC; s++) g_part[gb + s] = tv[s];
        }
    }
}

// ---------------------------------------------------------------------------
// Phase 2: merge 296 keys per row, tau = vhat3 - MARGIN2, exact fp32 rerank
// of ALL survivors (no caps), exact tie rules via keys. One block per row.
// ---------------------------------------------------------------------------
__global__ __launch_bounds__(256) void phase2_kernel(
        const float* __restrict__ x, const float* __restrict__ tr,
        const float* __restrict__ feat, const int* __restrict__ labels,
        float* __restrict__ out, int out_size) {
    const int b   = blockIdx.x;
    const int tid = threadIdx.x;

    __shared__ float xs[F_], fs[F_];
    __shared__ unsigned long long wbuf[24];
    __shared__ float s_tau;

    if (tid < F_) {
        xs[tid] = x[(size_t)b * F_ + tid];
        fs[tid] = feat[tid];
    }

    unsigned long long loc[2];
    int nloc = 0;
    for (int i = tid; i < NPART; i += 256) loc[nloc++] = g_part[(size_t)b * NPART + i];
    __syncthreads();

    unsigned long long s[3] = {0ull, 0ull, 0ull};
    for (int j = 0; j < nloc; j++) ins3(s, loc[j]);
    top3_reduce(s, wbuf, tid);
    if (tid == 0) s_tau = unordf((unsigned)(s[2] >> 32)) - MARGIN2;
    __syncthreads();
    const float tau = s_tau;
    const float lb  = g_left[b];

    unsigned long long t3[3] = {0ull, 0ull, 0ull};
    for (int j = 0; j < nloc; j++) {
        unsigned idx = ~(unsigned)loc[j];
        float vh = unordf((unsigned)(loc[j] >> 32));
        if (idx < (unsigned)N_ && vh >= tau) {
            const float4* trow = (const float4*)(tr + (size_t)idx * F_);
            float dot = 0.0f;
            #pragma unroll
            for (int k4 = 0; k4 < 32; k4++) {
                float4 tv = __ldg(&trow[k4]);
                dot = fmaf(xs[k4 * 4 + 0], fs[k4 * 4 + 0] * tv.x, dot);
                dot = fmaf(xs[k4 * 4 + 1], fs[k4 * 4 + 1] * tv.y, dot);
                dot = fmaf(xs[k4 * 4 + 2], fs[k4 * 4 + 2] * tv.z, dot);
                dot = fmaf(xs[k4 * 4 + 3], fs[k4 * 4 + 3] * tv.w, dot);
            }
            float v = fmaf(2.0f, dot, -sqrtf(lb + g_right[idx]));
            ins3(t3, mkkey(v, (int)idx));
        }
    }
    __syncthreads();
    top3_reduce(t3, wbuf, tid);

    if (tid == 0) {
        float v0 = unordf((unsigned)(t3[0] >> 32));
        float v1 = unordf((unsigned)(t3[1] >> 32));
        float v2 = unordf((unsigned)(t3[2] >> 32));
        int   i0 = (int)(~(unsigned)t3[0]);
        int   i1 = (int)(~(unsigned)t3[1]);
        int   i2 = (int)(~(unsigned)t3[2]);
        int l0 = labels[i0], l1 = labels[i1], l2 = labels[i2];
        int o = (l0 + l1 + l2) / 3;

        if (out_size >= B_ * NLBL) {
            #pragma unroll
            for (int j = 0; j < NLBL; j++) out[b * NLBL + j] = (j == o) ? 1.0f : 0.0f;
        }
        const int V0 = B_ * NLBL;
        if (out_size >= V0 + B_ * 3) {
            out[V0 + b * 3 + 0] = v0; out[V0 + b * 3 + 1] = v1; out[V0 + b * 3 + 2] = v2;
        }
        const int I0 = V0 + B_ * 3;
        if (out_size >= I0 + B_ * 3) {
            out[I0 + b * 3 + 0] = (float)i0; out[I0 + b * 3 + 1] = (float)i1;
            out[I0 + b * 3 + 2] = (float)i2;
        }
        const int L0 = I0 + B_ * 3;
        if (out_size >= L0 + B_ * 3) {
            out[L0 + b * 3 + 0] = (float)l0; out[L0 + b * 3 + 1] = (float)l1;
            out[L0 + b * 3 + 2] = (float)l2;
        }
    }
}

// ---------------------------------------------------------------------------
extern "C" void kernel_launch(void* const* d_in, const int* in_sizes, int n_in,
                              void* d_out, int out_size) {
    const float* x    = nullptr;
    const float* tr   = nullptr;
    const int*   lbl  = nullptr;
    const float* feat = nullptr;
    for (int i = 0; i < n_in; i++) {
        switch (in_sizes[i]) {
            case B_ * F_: x    = (const float*)d_in[i]; break;
            case N_ * F_: tr   = (const float*)d_in[i]; break;
            case N_:      lbl  = (const int*)  d_in[i]; break;
            case F_:      feat = (const float*)d_in[i]; break;
            default: break;
        }
    }

    cudaFuncSetAttribute(knn_hybrid, cudaFuncAttributeMaxDynamicSharedMemorySize,
                         SMEM_TOTAL);

    prep_kernel<<<(B_ + N_) / 8, 256>>>(x, tr, feat);
    knn_hybrid<<<dim3(16, NSPLIT), 256, SMEM_TOTAL>>>(tr);
    phase2_kernel<<<B_, 256>>>(x, tr, feat, lbl, (float*)d_out, out_size);
}

// round 17
// speedup vs baseline: 1.7598x; 1.7598x over previous
#include <cuda_runtime.h>
#include <cuda_fp16.h>
#include <math.h>
#include <float.h>
#include <limits.h>
#include <stdint.h>

// Problem constants
#define B_     2048
#define N_     65536
#define F_     128
#define KSTEPS (F_ / 16)       // 8
#define NSPLIT 37              // 16 x 37 = 592 CTAs = exactly 2 waves at occ 2
#define BN     64
#define NLBL   10
#define MARGIN2 0.5f           // phase-2 margin (>=5x fp16 vhat error bound)
#define PTOP   4               // per-thread top depth
#define TPC    8               // keys kept per (row, split)
#define NPART  (NSPLIT * TPC)  // 296
#define NSTAGE 3               // cp.async pipeline depth for B tiles

#define KPH    136             // padded row stride in halfs (272B)
#define KPB    (KPH * 2)
#define AS_BYTES (128 * KPB)   // 34816
#define BS_BYTES (64 * KPB)    // 17408
#define SMEM_TOTAL (AS_BYTES + NSTAGE * BS_BYTES)   // 87040 (occ 2: 174KB OK)

// ---------------------------------------------------------------------------
// Static device scratch
// ---------------------------------------------------------------------------
__device__ __align__(16) __half g_xe[(size_t)B_ * F_];   // fp16(x*feat)
__device__ __align__(16) __half g_te[(size_t)N_ * F_];   // fp16(tr*feat)
__device__ float g_left[B_];
__device__ float g_right[N_];
__device__ unsigned long long g_part[(size_t)B_ * NPART]; // sortable keys

// ---------------------------------------------------------------------------
// Helpers
// ---------------------------------------------------------------------------
__device__ __forceinline__ uint32_t smem_u32(const void* p) {
    uint32_t a;
    asm("{ .reg .u64 t; cvta.to.shared.u64 t, %1; cvt.u32.u64 %0, t; }" : "=r"(a) : "l"(p));
    return a;
}
#define CP16(dst, src) \
    asm volatile("cp.async.cg.shared.global [%0], [%1], 16;" :: "r"(dst), "l"(src))
#define CPCOMMIT() asm volatile("cp.async.commit_group;" ::: "memory")
#define CPWAIT(n)  asm volatile("cp.async.wait_group %0;" :: "n"(n) : "memory")

#define LDSM4(r0, r1, r2, r3, addr) \
    asm volatile("ldmatrix.sync.aligned.m8n8.x4.shared.b16 {%0,%1,%2,%3}, [%4];" \
                 : "=r"(r0), "=r"(r1), "=r"(r2), "=r"(r3) : "r"(addr))

#define MMA16816(c, a, b0, b1) \
    asm volatile("mma.sync.aligned.m16n8k16.row.col.f32.f16.f16.f32 " \
                 "{%0,%1,%2,%3},{%4,%5,%6,%7},{%8,%9},{%0,%1,%2,%3};" \
                 : "+f"((c)[0]), "+f"((c)[1]), "+f"((c)[2]), "+f"((c)[3]) \
                 : "r"((a)[0]), "r"((a)[1]), "r"((a)[2]), "r"((a)[3]), \
                   "r"(b0), "r"(b1))

// Order-preserving float<->uint maps (exact bit round-trip)
__device__ __forceinline__ unsigned ordf(float v) {
    unsigned u = __float_as_uint(v);
    return (u & 0x80000000u) ? ~u : (u | 0x80000000u);
}
__device__ __forceinline__ float unordf(unsigned u) {
    return __uint_as_float((u & 0x80000000u) ? (u ^ 0x80000000u) : ~u);
}
// key order == jax top_k order: higher v wins; ties -> lower idx wins
__device__ __forceinline__ unsigned long long mkkey(float v, int i) {
    return ((unsigned long long)ordf(v) << 32) | (unsigned)(~i);
}
__device__ __forceinline__ void ins3(unsigned long long* s, unsigned long long k) {
    if (k > s[2]) {
        s[2] = k;
        if (s[2] > s[1]) { unsigned long long t = s[1]; s[1] = s[2]; s[2] = t; }
        if (s[1] > s[0]) { unsigned long long t = s[0]; s[0] = s[1]; s[1] = t; }
    }
}
// Block-wide top-3 key reduction (256 threads). tid 0 ends with global top-3.
__device__ __forceinline__ void top3_reduce(unsigned long long* s,
                                            unsigned long long* wbuf, int tid) {
    #pragma unroll
    for (int off = 16; off; off >>= 1) {
        unsigned long long r0 = __shfl_xor_sync(0xffffffffu, s[0], off);
        unsigned long long r1 = __shfl_xor_sync(0xffffffffu, s[1], off);
        unsigned long long r2 = __shfl_xor_sync(0xffffffffu, s[2], off);
        ins3(s, r0); ins3(s, r1); ins3(s, r2);
    }
    int w = tid >> 5, lane = tid & 31;
    if (lane == 0) { wbuf[w * 3] = s[0]; wbuf[w * 3 + 1] = s[1]; wbuf[w * 3 + 2] = s[2]; }
    __syncthreads();
    if (tid == 0)
        for (int i = 3; i < 24; i++) ins3(s, wbuf[i]);
}

// ---------------------------------------------------------------------------
// Prep: fp16 of x*feat / tr*feat + fp32 norms. One warp per row.
// ---------------------------------------------------------------------------
__global__ void prep_kernel(const float* __restrict__ x,
                            const float* __restrict__ tr,
                            const float* __restrict__ feat) {
    int g    = blockIdx.x * blockDim.x + threadIdx.x;
    int w    = g >> 5;
    int lane = threadIdx.x & 31;
    float4 f = ((const float4*)feat)[lane];

    float wv[4];
    bool isx = (w < B_);
    int row;
    if (isx) {
        row = w;
        float4 v = ((const float4*)x)[row * 32 + lane];
        wv[0] = v.x * f.x; wv[1] = v.y * f.y; wv[2] = v.z * f.z; wv[3] = v.w * f.w;
        float s = v.x * v.x + v.y * v.y + v.z * v.z + v.w * v.w;  // raw x^2
        #pragma unroll
        for (int o = 16; o; o >>= 1) s += __shfl_xor_sync(0xffffffffu, s, o);
        if (lane == 0) g_left[row] = s;
    } else if (w < B_ + N_) {
        row = w - B_;
        float4 v = ((const float4*)tr)[(size_t)row * 32 + lane];
        wv[0] = v.x * f.x; wv[1] = v.y * f.y; wv[2] = v.z * f.z; wv[3] = v.w * f.w;
        float s = wv[0]*wv[0] + wv[1]*wv[1] + wv[2]*wv[2] + wv[3]*wv[3];
        #pragma unroll
        for (int o = 16; o; o >>= 1) s += __shfl_xor_sync(0xffffffffu, s, o);
        if (lane == 0) g_right[row] = s;
    } else {
        return;
    }

    ushort4 th_;
    unsigned short* ph = &th_.x;
    #pragma unroll
    for (int j = 0; j < 4; j++) ph[j] = __half_as_ushort(__float2half_rn(wv[j]));
    size_t base = (size_t)row * F_ + lane * 4;
    if (isx) *(ushort4*)&g_xe[base] = th_;
    else     *(ushort4*)&g_te[base] = th_;
}

// ---------------------------------------------------------------------------
// Phase 1: fp16 HMMA GEMM (K=128), 3-stage cp.async pipeline, ONE barrier
// per tile. Per-thread top-4, CTA merge to top-8 keys per (row, split).
// Grid (16, 37), 256 threads, occ 2, 2 exact waves.
// ---------------------------------------------------------------------------
__global__ __launch_bounds__(256, 2) void knn_f16() {
    extern __shared__ char smem[];
    const uint32_t asB  = smem_u32(smem);
    const uint32_t bsB0 = asB + AS_BYTES;

    const int tid  = threadIdx.x;
    const int lane = tid & 31;
    const int wid  = tid >> 5;
    const int wm   = wid & 3;
    const int wn   = wid >> 2;
    const int mblk = blockIdx.x;
    const int nsp  = blockIdx.y;
    const int tstart = nsp * 27 + min(nsp, 25);     // uneven split of 1024 tiles
    const int tcount = 27 + (nsp < 25 ? 1 : 0);

    // Prologue group 0: A block (128 x 128 halfs) + B tile 0
    {
        const __half* src = g_xe + (size_t)mblk * 128 * F_;
        #pragma unroll
        for (int j = 0; j < 8; j++) {
            int i = tid + j * 256;
            int row = i >> 4, kc = i & 15;
            CP16(asB + row * KPB + kc * 16, src + (size_t)row * F_ + kc * 8);
        }
        int nb0 = tstart * BN;
        #pragma unroll
        for (int j = 0; j < 4; j++) {
            int i = tid + j * 256;
            int row = i >> 4, kc = i & 15;
            CP16(bsB0 + row * KPB + kc * 16,
                 g_te + (size_t)(nb0 + row) * F_ + kc * 8);
        }
    }
    CPCOMMIT();
    // Prologue group 1: B tile 1 (empty group if tcount == 1)
    if (1 < tcount) {
        int nb1 = (tstart + 1) * BN;
        #pragma unroll
        for (int j = 0; j < 4; j++) {
            int i = tid + j * 256;
            int row = i >> 4, kc = i & 15;
            CP16(bsB0 + BS_BYTES + row * KPB + kc * 16,
                 g_te + (size_t)(nb1 + row) * F_ + kc * 8);
        }
    }
    CPCOMMIT();

    // Per-thread rows r = mt*2+cp; per-row top-4 (vhat, idx) in registers
    float lft[4];
    float bv[4][PTOP];
    int   bi[4][PTOP];
    #pragma unroll
    for (int r = 0; r < 4; r++) {
        int mt = r >> 1, cp = r & 1;
        lft[r] = g_left[mblk * 128 + wm * 32 + mt * 16 + cp * 8 + (lane >> 2)];
        #pragma unroll
        for (int s = 0; s < PTOP; s++) { bv[r][s] = -FLT_MAX; bi[r][s] = INT_MAX; }
    }

    const uint32_t laneA = (uint32_t)((((lane >> 3) & 1) * 8 + (lane & 7)) * KPB
                                      + (lane >> 4) * 16);
    const uint32_t laneB = (uint32_t)((((lane >> 4) << 3) + (lane & 7)) * KPB
                                      + ((lane >> 3) & 1) * 16);
    const uint32_t aAddr0 = asB + (wm * 32) * KPB + laneA;
    const uint32_t aAddr1 = asB + (wm * 32 + 16) * KPB + laneA;

    int stage = 0;   // stage of tile t; cycles 0,1,2,0,...
    for (int t = 0; t < tcount; t++) {
        // Wait: all but the newest committed group done => tile t's group done.
        CPWAIT(1);
        __syncthreads();   // the ONLY barrier per tile

        // Prefetch tile t+2 into stage (t+2)%3 == (t-1)%3 (safe: every thread
        // finished reading that stage before the barrier above). Uniform
        // commit keeps group accounting aligned with the CPWAIT(1) above.
        if (t + 2 < tcount) {
            int ps = stage + 2;
            if (ps >= NSTAGE) ps -= NSTAGE;
            uint32_t bsN = bsB0 + ps * BS_BYTES;
            int nb = (tstart + t + 2) * BN;
            #pragma unroll
            for (int j = 0; j < 4; j++) {
                int i = tid + j * 256;
                int row = i >> 4, kc = i & 15;
                CP16(bsN + row * KPB + kc * 16,
                     g_te + (size_t)(nb + row) * F_ + kc * 8);
            }
        }
        CPCOMMIT();

        const uint32_t bsS = bsB0 + stage * BS_BYTES;
        const uint32_t bAddr0 = bsS + (wn * 32) * KPB + laneB;
        const uint32_t bAddr1 = bsS + (wn * 32 + 16) * KPB + laneB;

        float acc[2][4][4];
        #pragma unroll
        for (int mt = 0; mt < 2; mt++)
            #pragma unroll
            for (int nt = 0; nt < 4; nt++)
                #pragma unroll
                for (int c = 0; c < 4; c++) acc[mt][nt][c] = 0.0f;

        #pragma unroll
        for (int ks = 0; ks < KSTEPS; ks++) {
            const uint32_t ko = ks * 32;
            uint32_t a0[4], a1[4], b01[4], b23[4];
            LDSM4(a0[0], a0[1], a0[2], a0[3], aAddr0 + ko);
            LDSM4(a1[0], a1[1], a1[2], a1[3], aAddr1 + ko);
            LDSM4(b01[0], b01[1], b01[2], b01[3], bAddr0 + ko);
            LDSM4(b23[0], b23[1], b23[2], b23[3], bAddr1 + ko);
            MMA16816(acc[0][0], a0, b01[0], b01[1]);
            MMA16816(acc[0][1], a0, b01[2], b01[3]);
            MMA16816(acc[0][2], a0, b23[0], b23[1]);
            MMA16816(acc[0][3], a0, b23[2], b23[3]);
            MMA16816(acc[1][0], a1, b01[0], b01[1]);
            MMA16816(acc[1][1], a1, b01[2], b01[3]);
            MMA16816(acc[1][2], a1, b23[0], b23[1]);
            MMA16816(acc[1][3], a1, b23[2], b23[3]);
        }

        // ---- Epilogue: vhat = 2*acc - sqrt(l+r); per-row top-4 insert ----
        const int cbase = (tstart + t) * BN + wn * 32;
        float2 rt2[4];
        const float2* rp = (const float2*)(g_right + cbase + 2 * (lane & 3));
        #pragma unroll
        for (int nt = 0; nt < 4; nt++) rt2[nt] = __ldg(rp + nt * 4);

        float rm = fminf(fminf(fminf(rt2[0].x, rt2[0].y), fminf(rt2[1].x, rt2[1].y)),
                         fminf(fminf(rt2[2].x, rt2[2].y), fminf(rt2[3].x, rt2[3].y)));
        #pragma unroll
        for (int o = 16; o; o >>= 1)
            rm = fminf(rm, __shfl_xor_sync(0xffffffffu, rm, o));

        float subnd[4];
        #pragma unroll
        for (int r = 0; r < 4; r++) subnd[r] = sqrtf(lft[r] + rm);

        #pragma unroll
        for (int mt = 0; mt < 2; mt++) {
            #pragma unroll
            for (int nt = 0; nt < 4; nt++) {
                const int colb = cbase + nt * 8 + 2 * (lane & 3);
                #pragma unroll
                for (int e = 0; e < 4; e++) {
                    const int r   = mt * 2 + (e >> 1);
                    const int idx = colb + (e & 1);
                    const float rt = (e & 1) ? rt2[nt].y : rt2[nt].x;
                    float a  = acc[mt][nt][(e >> 1) * 2 + (e & 1)];
                    float ub = fmaf(2.0f, a, -subnd[r]);     // upper bound
                    if (ub > bv[r][PTOP - 1]) {
                        float v = fmaf(2.0f, a, -sqrtf(lft[r] + rt));
                        if (v > bv[r][PTOP - 1]) {
                            bv[r][PTOP - 1] = v; bi[r][PTOP - 1] = idx;
                            #pragma unroll
                            for (int p = PTOP - 1; p > 0; p--) {
                                if (bv[r][p] > bv[r][p - 1]) {
                                    float tv = bv[r][p - 1]; int ti = bi[r][p - 1];
                                    bv[r][p - 1] = bv[r][p]; bi[r][p - 1] = bi[r][p];
                                    bv[r][p] = tv;           bi[r][p] = ti;
                                }
                            }
                        }
                    }
                }
            }
        }

        if (++stage == NSTAGE) stage = 0;
        // no trailing barrier: next iteration's prefetch comes after its own
        // CPWAIT + __syncthreads and targets the stage retired two tiles ago.
    }

    // ---- CTA merge: 8 threads x 4 entries -> top-8 keys per row ---------
    __syncthreads();   // all LDSM reads of As done before smem reuse
    unsigned long long* mrg = (unsigned long long*)smem;  // [128 rows][32]
    const int slotb = (wn * 4 + (lane & 3)) * PTOP;
    #pragma unroll
    for (int r = 0; r < 4; r++) {
        int mt = r >> 1, cp = r & 1;
        int row = wm * 32 + mt * 16 + cp * 8 + (lane >> 2);
        #pragma unroll
        for (int s = 0; s < PTOP; s++)
            mrg[row * 32 + slotb + s] = mkkey(bv[r][s], bi[r][s]);
    }
    __syncthreads();

    if (tid < 128) {
        unsigned long long tv[TPC];
        #pragma unroll
        for (int s = 0; s < TPC; s++) tv[s] = 0ull;
        #pragma unroll 4
        for (int c = 0; c < 32; c++) {
            unsigned long long k = mrg[tid * 32 + c];
            if (k > tv[TPC - 1]) {
                tv[TPC - 1] = k;
                #pragma unroll
                for (int p = TPC - 1; p > 0; p--) {
                    if (tv[p] > tv[p - 1]) {
                        unsigned long long t2 = tv[p - 1];
                        tv[p - 1] = tv[p]; tv[p] = t2;
                    }
                }
            }
        }
        size_t gb = ((size_t)(mblk * 128 + tid) * NSPLIT + nsp) * TPC;
        #pragma unroll
        for (int s = 0; s < TPC; s++) g_part[gb + s] = tv[s];
    }
}

// ---------------------------------------------------------------------------
// Phase 2: merge 296 keys per row, tau = vhat3 - MARGIN2, exact fp32 rerank
// of ALL survivors (no caps), exact tie rules via keys. One block per row.
// ---------------------------------------------------------------------------
__global__ __launch_bounds__(256) void phase2_kernel(
        const float* __restrict__ x, const float* __restrict__ tr,
        const float* __restrict__ feat, const int* __restrict__ labels,
        float* __restrict__ out, int out_size) {
    const int b   = blockIdx.x;
    const int tid = threadIdx.x;

    __shared__ float xs[F_], fs[F_];
    __shared__ unsigned long long wbuf[24];
    __shared__ float s_tau;

    if (tid < F_) {
        xs[tid] = x[(size_t)b * F_ + tid];
        fs[tid] = feat[tid];
    }

    // Local partial keys (<=2 per thread: 296/256)
    unsigned long long loc[2];
    int nloc = 0;
    for (int i = tid; i < NPART; i += 256) loc[nloc++] = g_part[(size_t)b * NPART + i];
    __syncthreads();

    // Stage A: top-3 by vhat
    unsigned long long s[3] = {0ull, 0ull, 0ull};
    for (int j = 0; j < nloc; j++) ins3(s, loc[j]);
    top3_reduce(s, wbuf, tid);
    if (tid == 0) s_tau = unordf((unsigned)(s[2] >> 32)) - MARGIN2;
    __syncthreads();
    const float tau = s_tau;
    const float lb  = g_left[b];

    // Stage B: exact rerank of every survivor
    unsigned long long t3[3] = {0ull, 0ull, 0ull};
    for (int j = 0; j < nloc; j++) {
        unsigned idx = ~(unsigned)loc[j];
        float vh = unordf((unsigned)(loc[j] >> 32));
        if (idx < (unsigned)N_ && vh >= tau) {
            const float4* trow = (const float4*)(tr + (size_t)idx * F_);
            float dot = 0.0f;
            #pragma unroll
            for (int k4 = 0; k4 < 32; k4++) {
                float4 tv = __ldg(&trow[k4]);
                dot = fmaf(xs[k4 * 4 + 0], fs[k4 * 4 + 0] * tv.x, dot);
                dot = fmaf(xs[k4 * 4 + 1], fs[k4 * 4 + 1] * tv.y, dot);
                dot = fmaf(xs[k4 * 4 + 2], fs[k4 * 4 + 2] * tv.z, dot);
                dot = fmaf(xs[k4 * 4 + 3], fs[k4 * 4 + 3] * tv.w, dot);
            }
            float v = fmaf(2.0f, dot, -sqrtf(lb + g_right[idx]));
            ins3(t3, mkkey(v, (int)idx));
        }
    }
    __syncthreads();   // wbuf reuse
    top3_reduce(t3, wbuf, tid);

    if (tid == 0) {
        float v0 = unordf((unsigned)(t3[0] >> 32));
        float v1 = unordf((unsigned)(t3[1] >> 32));
        float v2 = unordf((unsigned)(t3[2] >> 32));
        int   i0 = (int)(~(unsigned)t3[0]);
        int   i1 = (int)(~(unsigned)t3[1]);
        int   i2 = (int)(~(unsigned)t3[2]);
        int l0 = labels[i0], l1 = labels[i1], l2 = labels[i2];
        int o = (l0 + l1 + l2) / 3;

        if (out_size >= B_ * NLBL) {
            #pragma unroll
            for (int j = 0; j < NLBL; j++) out[b * NLBL + j] = (j == o) ? 1.0f : 0.0f;
        }
        const int V0 = B_ * NLBL;
        if (out_size >= V0 + B_ * 3) {
            out[V0 + b * 3 + 0] = v0; out[V0 + b * 3 + 1] = v1; out[V0 + b * 3 + 2] = v2;
        }
        const int I0 = V0 + B_ * 3;
        if (out_size >= I0 + B_ * 3) {
            out[I0 + b * 3 + 0] = (float)i0; out[I0 + b * 3 + 1] = (float)i1;
            out[I0 + b * 3 + 2] = (float)i2;
        }
        const int L0 = I0 + B_ * 3;
        if (out_size >= L0 + B_ * 3) {
            out[L0 + b * 3 + 0] = (float)l0; out[L0 + b * 3 + 1] = (float)l1;
            out[L0 + b * 3 + 2] = (float)l2;
        }
    }
}

// ---------------------------------------------------------------------------
extern "C" void kernel_launch(void* const* d_in, const int* in_sizes, int n_in,
                              void* d_out, int out_size) {
    const float* x    = nullptr;
    const float* tr   = nullptr;
    const int*   lbl  = nullptr;
    const float* feat = nullptr;
    for (int i = 0; i < n_in; i++) {
        switch (in_sizes[i]) {
            case B_ * F_: x    = (const float*)d_in[i]; break;
            case N_ * F_: tr   = (const float*)d_in[i]; break;
            case N_:      lbl  = (const int*)  d_in[i]; break;
            case F_:      feat = (const float*)d_in[i]; break;
            default: break;
        }
    }

    cudaFuncSetAttribute(knn_f16, cudaFuncAttributeMaxDynamicSharedMemorySize,
                         SMEM_TOTAL);

    prep_kernel<<<(B_ + N_) / 8, 256>>>(x, tr, feat);
    knn_f16<<<dim3(16, NSPLIT), 256, SMEM_TOTAL>>>();
    phase2_kernel<<<B_, 256>>>(x, tr, feat, lbl, (float*)d_out, out_size);
}